// round 15
// baseline (speedup 1.0000x reference)
#include <cuda_runtime.h>

// Problem constants (fixed by the reference: B=8, N=4096, D=2)
#define BQ       8
#define NPTS     4096
#define NSETS    16                  // 8 batches x {y_true, y_pred}
#define NBINS    512
#define XMAX     5.0f
#define BINW     (2.0f * XMAX / NBINS)
#define BSCALE   (NBINS / (2.0f * XMAX))
#define PTHREADS 512
#define STHREADS 512
#define NB_B     128                 // search blocks: 8 tiles x 8 batches x 2 dirs
#define NPART    (NB_B + NSETS)      // 144 partials (128 chamfer + 16 EMD slots)

// Scratch (device globals — allocation-free per harness rules)
__device__ float2 g_pts[NSETS][NPTS];            // stably bin-sorted points
__device__ int    g_binStart[NSETS][NBINS + 1];  // bin b occupies [start[b], start[b+1])
__device__ float  g_partials[NPART];
__device__ int    g_counter = 0;                 // reset by last search block

__device__ __forceinline__ int binOf(float x) {
    int b = (int)((x + XMAX) * BSCALE);
    return min(max(b, 0), NBINS - 1);
}
__device__ __forceinline__ float binEdge(int b) {   // left edge of bin b
    return -XMAX + (float)b * BINW;
}

// ───────── Kernel A: EMD partial + STABLE counting sort by x-bin ─────────────
// Block s handles set s: t = s&1 (0 = y_true, 1 = y_pred), batch = s>>1.
// Stability (original-index order within each bin) makes the sorted layout —
// and therefore the search kernel's thread<->query map — fully deterministic.
__global__ __launch_bounds__(PTHREADS, 1)
void prep_kernel(const float* __restrict__ yt, const float* __restrict__ yp) {
    __shared__ int   slot[NPTS];        // bin id, then overwritten with dest rank (16 KB)
    __shared__ int   hist[NBINS];       // histogram, then rank cursors (2 KB)
    __shared__ int   scn[NBINS];        // scan workspace (2 KB)
    __shared__ int   start[NBINS + 1];  // exclusive prefix (2 KB)
    __shared__ float red[PTHREADS];     // (2 KB)

    const int tid = threadIdx.x;
    const int s   = blockIdx.x;
    const int t   = s & 1;
    const int b   = s >> 1;
    const float2* src = reinterpret_cast<const float2*>((t ? yp : yt)) + (size_t)b * NPTS;

    // EMD partial (index-aligned pairs); t==0 blocks compute, t==1 write 0.
    float e = 0.0f;
    if (t == 0) {
        const float2* T = reinterpret_cast<const float2*>(yt) + (size_t)b * NPTS;
        const float2* P = reinterpret_cast<const float2*>(yp) + (size_t)b * NPTS;
        for (int i = tid; i < NPTS; i += PTHREADS) {
            const float2 tv = T[i], pv = P[i];
            const float d0 = tv.x - pv.x;
            const float d1 = (tv.x + tv.y) - (pv.x + pv.y);
            e = fmaf(d0, d0, e);
            e = fmaf(d1, d1, e);
        }
    }
    red[tid] = e;
    __syncthreads();
    for (int w = PTHREADS / 2; w > 0; w >>= 1) {
        if (tid < w) red[tid] += red[tid + w];
        __syncthreads();
    }
    if (tid == 0)
        g_partials[NB_B + s] = (t == 0) ? red[0] * (1.0f / ((float)BQ * NPTS * 2)) : 0.0f;

    // Bin ids + histogram (counts are order-invariant).
    if (tid < NBINS) hist[tid] = 0;
    __syncthreads();
    for (int i = tid; i < NPTS; i += PTHREADS) {
        const int bb = binOf(src[i].x);
        slot[i] = bb;
        atomicAdd(&hist[bb], 1);
    }
    __syncthreads();

    // Inclusive scan over 512 bins (Hillis–Steele).
    if (tid < NBINS) scn[tid] = hist[tid];
    __syncthreads();
    for (int off = 1; off < NBINS; off <<= 1) {
        int v = 0;
        if (tid < NBINS && tid >= off) v = scn[tid - off];
        __syncthreads();
        if (tid < NBINS) scn[tid] += v;
        __syncthreads();
    }
    if (tid == 0) start[0] = 0;
    if (tid < NBINS) start[tid + 1] = scn[tid];
    __syncthreads();                           // ── FIX: start[] fully written
    if (tid < NBINS) hist[tid] = start[tid];   //    before cursors read it
    __syncthreads();

    // Warp 0: stable rank assignment in original index order (deterministic).
    // 128 rounds of 32 points; within a round, __match_any + lane order gives
    // index-ordered ranks; cursors advance once per (round, bin).
    if (tid < 32) {
        const int lane = tid;
        for (int c = 0; c < NPTS / 32; c++) {
            const int i  = c * 32 + lane;
            const int bb = slot[i];
            const unsigned mask = __match_any_sync(0xffffffffu, bb);
            const int lead = __ffs(mask) - 1;
            const int rnk  = __popc(mask & ((1u << lane) - 1));
            int base = 0;
            if (lane == lead) base = hist[bb];
            base = __shfl_sync(0xffffffffu, base, lead);
            slot[i] = base + rnk;                       // destination rank
            if (lane == lead) hist[bb] = base + __popc(mask);
            __syncwarp();
        }
    }
    __syncthreads();

    // Scatter (coalesced read, deterministic destination).
    for (int i = tid; i < NPTS; i += PTHREADS)
        g_pts[s][slot[i]] = src[i];
    for (int i = tid; i <= NBINS; i += PTHREADS)
        g_binStart[s][i] = start[i];
}

// ───────── Kernel B: exact NN, queries in sorted order (convergent warps) ────
// Grid (8 tiles, 8 batches, 2 dirs); thread t owns sorted-rank query
// blockIdx.x*512 + t. Adjacent lanes share bins -> LDS broadcasts, uniform
// trip counts, minimal divergence. Thread<->query map is deterministic
// because the sort is stable.
__global__ __launch_bounds__(STHREADS, 1)
void search_kernel(float* __restrict__ out) {
    __shared__ float2 shPts[NPTS];        // 32 KB: bin-sorted reference set
    __shared__ int    shStart[NBINS + 1]; //  2 KB
    __shared__ float  red[STHREADS];      //  2 KB
    __shared__ bool   isLast;

    const int tid = threadIdx.x;
    const int dir = blockIdx.z;
    const int b   = blockIdx.y;
    const int sq  = (b << 1) | dir;          // query set
    const int sr  = (b << 1) | (1 - dir);    // reference set

    // Stage reference set + bin index (coalesced).
    for (int i = tid; i < NPTS; i += STHREADS) shPts[i] = g_pts[sr][i];
    for (int i = tid; i <= NBINS; i += STHREADS) shStart[i] = g_binStart[sr][i];
    __syncthreads();

    // Query in sorted order.
    const float2 q = g_pts[sq][blockIdx.x * STHREADS + tid];
    const int qb = binOf(q.x);

    float best = 1e30f;
    // Home bin (lanes share qb -> broadcast LDS, same trip count).
    for (int j = shStart[qb]; j < shStart[qb + 1]; j++) {
        const float2 r = shPts[j];
        const float dx = r.x - q.x, dy = r.y - q.y;
        best = fminf(best, fmaf(dx, dx, dy * dy));
    }
    // Certificate expansion: every unscanned point has |dx| >= gap (exact).
    int lo = qb, hi = qb;
    for (;;) {
        const float lgap = (lo > 0)         ? (q.x - binEdge(lo))     : __int_as_float(0x7f800000);
        const float rgap = (hi < NBINS - 1) ? (binEdge(hi + 1) - q.x) : __int_as_float(0x7f800000);
        const float gap  = fminf(lgap, rgap);
        if (gap * gap >= best) break;
        int nb;
        if (lgap <= rgap) { lo--; nb = lo; } else { hi++; nb = hi; }
        for (int j = shStart[nb]; j < shStart[nb + 1]; j++) {
            const float2 r = shPts[j];
            const float dx = r.x - q.x, dy = r.y - q.y;
            best = fminf(best, fmaf(dx, dx, dy * dy));
        }
    }

    // Chamfer contribution (d2 >= 0 by construction, matches reference clamp).
    const float local = best * (1.0f / BQ);

    // Deterministic block tree reduction (stable sort -> fixed map -> fixed order).
    red[tid] = local;
    __syncthreads();
    for (int w = STHREADS / 2; w > 0; w >>= 1) {
        if (tid < w) red[tid] += red[tid + w];
        __syncthreads();
    }
    const int bid = (blockIdx.z * gridDim.y + blockIdx.y) * gridDim.x + blockIdx.x;
    if (tid == 0) {
        g_partials[bid] = red[0];
        __threadfence();
        const int c = atomicAdd(&g_counter, 1);
        isLast = (c == NB_B - 1);
    }
    __syncthreads();

    // Last block: deterministic fixed-order sum of all 144 partials.
    if (isLast) {
        float v = 0.0f;
        if (tid < NPART) {
            __threadfence();
            v = *((volatile float*)&g_partials[tid]);
        }
        red[tid] = v;
        __syncthreads();
        for (int w = STHREADS / 2; w > 0; w >>= 1) {
            if (tid < w) red[tid] += red[tid + w];
            __syncthreads();
        }
        if (tid == 0) {
            out[0] = red[0];
            g_counter = 0;   // reset for next graph replay
        }
    }
}

extern "C" void kernel_launch(void* const* d_in, const int* in_sizes, int n_in,
                              void* d_out, int out_size) {
    const float* y_true = (const float*)d_in[0];
    const float* y_pred = (const float*)d_in[1];
    float* out = (float*)d_out;

    prep_kernel<<<NSETS, PTHREADS>>>(y_true, y_pred);
    dim3 grid(NPTS / STHREADS, BQ, 2);   // (8, 8, 2)
    search_kernel<<<grid, STHREADS>>>(out);
}